// round 2
// baseline (speedup 1.0000x reference)
#include <cuda_runtime.h>
#include <math.h>

#define NB 2
#define NS 2048
#define ND 1024
#define NH 16
#define NDK 64

// ---------------- scratch (static device globals; no allocation in kernel_launch) ----
__device__ float g_qs[NB * NH * NS * NDK];            // [b][h][s][k]   16.8 MB
__device__ float g_ks[NB * NH * NS * NDK];            // [b][h][s][k]   16.8 MB
__device__ float g_vs[NB * NS * NDK];                 // [b][s][k]       2 MB
__device__ float g_head[NB * NS * NDK];               // [b][s][k]       2 MB
__device__ float g_scores[(size_t)NB * NH * NS * NS]; // [b][h][s][t]  536 MB

// ---------------- generic 64x64-tile fp32 GEMM, 4x4 per thread, 256 threads ---------
// C[m,n] = alpha * sum_k A[m,k] * (BT ? B[n,k] : B[k,n])
// A row-major lda=K; B row-major ldb = (BT ? K : N); C row-major ldc=N.
// Batched via blockIdx.z with element strides sA/sB/sC.
template <bool BT>
__global__ __launch_bounds__(256) void gemm64(
    const float* __restrict__ Ab, const float* __restrict__ Bb, float* __restrict__ Cb,
    int M, int N, int K, long long sA, long long sB, long long sC, float alpha)
{
    const int BM = 64, BN = 64, BK = 16;
    __shared__ float As[BK][BM + 4];
    __shared__ float Bs[BK][BN + 4];

    const float* A = Ab + (size_t)blockIdx.z * sA;
    const float* B = Bb + (size_t)blockIdx.z * sB;
    float* C = Cb + (size_t)blockIdx.z * sC;

    int tid = threadIdx.x;
    int tx = tid & 15, ty = tid >> 4;
    int m0 = blockIdx.y * BM, n0 = blockIdx.x * BN;

    int la_r = tid >> 2;        // 0..63 : row within tile
    int la_c = (tid & 3) * 4;   // 0,4,8,12 : k offset (float4)

    float acc[4][4] = {};

    for (int k0 = 0; k0 < K; k0 += BK) {
        // A tile: [BM x BK] -> As[k][m]
        float4 av = *(const float4*)(A + (size_t)(m0 + la_r) * K + k0 + la_c);
        As[la_c + 0][la_r] = av.x;
        As[la_c + 1][la_r] = av.y;
        As[la_c + 2][la_r] = av.z;
        As[la_c + 3][la_r] = av.w;

        if (BT) {
            // B tile from [N x K]: load row n = n0+la_r, 4 k's -> Bs[k][n]
            float4 bv = *(const float4*)(B + (size_t)(n0 + la_r) * K + k0 + la_c);
            Bs[la_c + 0][la_r] = bv.x;
            Bs[la_c + 1][la_r] = bv.y;
            Bs[la_c + 2][la_r] = bv.z;
            Bs[la_c + 3][la_r] = bv.w;
        } else {
            // B tile from [K x N]: row k = k0 + (tid>>4), 4 n's
            int br = tid >> 4;          // 0..15
            int bc = (tid & 15) * 4;    // 0..60
            float4 bv = *(const float4*)(B + (size_t)(k0 + br) * N + n0 + bc);
            *(float4*)&Bs[br][bc] = bv;
        }
        __syncthreads();

#pragma unroll
        for (int k = 0; k < BK; k++) {
            float a[4], b[4];
#pragma unroll
            for (int i = 0; i < 4; i++) a[i] = As[k][ty * 4 + i];
#pragma unroll
            for (int j = 0; j < 4; j++) b[j] = Bs[k][tx * 4 + j];
#pragma unroll
            for (int i = 0; i < 4; i++)
#pragma unroll
                for (int j = 0; j < 4; j++) acc[i][j] += a[i] * b[j];
        }
        __syncthreads();
    }

#pragma unroll
    for (int i = 0; i < 4; i++) {
        int m = m0 + ty * 4 + i;
        float4 v = make_float4(acc[i][0] * alpha, acc[i][1] * alpha,
                               acc[i][2] * alpha, acc[i][3] * alpha);
        *(float4*)(C + (size_t)m * N + n0 + tx * 4) = v;
    }
}

// ---------------- per-head Q/K projection with scattered output -------------------
// z = blockIdx.z in [0, 2H): h = z & 15, which = z >> 4 (0 -> q/Wq/g_qs, 1 -> k/Wk/g_ks)
// C element (m, n): m = b*S + s -> out[((b*H+h)*S + s)*DK + n]
__global__ __launch_bounds__(256) void gemm_proj(
    const float* __restrict__ in_q, const float* __restrict__ in_k,
    const float* __restrict__ Wq, const float* __restrict__ Wk,
    float* __restrict__ out_qs, float* __restrict__ out_ks)
{
    const int BM = 64, BK = 16;
    __shared__ float As[BK][BM + 4];
    __shared__ float Bs[BK][NDK + 4];

    int z = blockIdx.z;
    int h = z & (NH - 1);
    int which = z >> 4;
    const float* A = which ? in_k : in_q;
    const float* W = (which ? Wk : Wq) + (size_t)h * ND * NDK;
    float* outp = which ? out_ks : out_qs;

    int m0 = blockIdx.y * BM;
    int b = m0 / NS;
    int srow = m0 % NS;
    float* C = outp + ((size_t)(b * NH + h) * NS + srow) * NDK;

    int tid = threadIdx.x;
    int tx = tid & 15, ty = tid >> 4;
    int la_r = tid >> 2;
    int la_c = (tid & 3) * 4;

    float acc[4][4] = {};

    for (int k0 = 0; k0 < ND; k0 += BK) {
        float4 av = *(const float4*)(A + (size_t)(m0 + la_r) * ND + k0 + la_c);
        As[la_c + 0][la_r] = av.x;
        As[la_c + 1][la_r] = av.y;
        As[la_c + 2][la_r] = av.z;
        As[la_c + 3][la_r] = av.w;

        int br = tid >> 4;
        int bc = (tid & 15) * 4;
        float4 bv = *(const float4*)(W + (size_t)(k0 + br) * NDK + bc);
        *(float4*)&Bs[br][bc] = bv;
        __syncthreads();

#pragma unroll
        for (int k = 0; k < BK; k++) {
            float a[4], b2[4];
#pragma unroll
            for (int i = 0; i < 4; i++) a[i] = As[k][ty * 4 + i];
#pragma unroll
            for (int j = 0; j < 4; j++) b2[j] = Bs[k][tx * 4 + j];
#pragma unroll
            for (int i = 0; i < 4; i++)
#pragma unroll
                for (int j = 0; j < 4; j++) acc[i][j] += a[i] * b2[j];
        }
        __syncthreads();
    }

#pragma unroll
    for (int i = 0; i < 4; i++) {
        float4 v = make_float4(acc[i][0], acc[i][1], acc[i][2], acc[i][3]);
        *(float4*)(C + (size_t)(ty * 4 + i) * NDK + tx * 4) = v;
    }
}

// ---------------- softmax over each score row + mean over heads -------------------
// One block per (b, s). For h = 0..15: load row, softmax, accumulate p/(Z*H) into
// per-thread registers (each thread owns fixed 8 columns). Write attn_mean row.
__device__ __forceinline__ float warp_max(float v) {
#pragma unroll
    for (int o = 16; o; o >>= 1) v = fmaxf(v, __shfl_xor_sync(0xFFFFFFFFu, v, o));
    return v;
}
__device__ __forceinline__ float warp_sum(float v) {
#pragma unroll
    for (int o = 16; o; o >>= 1) v += __shfl_xor_sync(0xFFFFFFFFu, v, o);
    return v;
}

__global__ __launch_bounds__(256) void softmax_mean(
    const float* __restrict__ scores, float* __restrict__ attn_mean)
{
    __shared__ float red[8];
    int bs = blockIdx.x;          // 0 .. B*S-1
    int tid = threadIdx.x;        // 256
    int wid = tid >> 5, lane = tid & 31;

    float acc[8] = {0.f, 0.f, 0.f, 0.f, 0.f, 0.f, 0.f, 0.f};

    for (int h = 0; h < NH; h++) {
        int b = bs / NS, s = bs % NS;
        const float4* row =
            (const float4*)(scores + ((size_t)(b * NH + h) * NS + s) * NS);
        float4 v0 = row[tid];
        float4 v1 = row[256 + tid];
        float vals[8] = {v0.x, v0.y, v0.z, v0.w, v1.x, v1.y, v1.z, v1.w};

        // block max
        float m = vals[0];
#pragma unroll
        for (int i = 1; i < 8; i++) m = fmaxf(m, vals[i]);
        m = warp_max(m);
        if (lane == 0) red[wid] = m;
        __syncthreads();
        float mm = red[0];
#pragma unroll
        for (int i = 1; i < 8; i++) mm = fmaxf(mm, red[i]);
        __syncthreads();

        // exp + block sum
        float e[8];
        float z = 0.f;
#pragma unroll
        for (int i = 0; i < 8; i++) { e[i] = __expf(vals[i] - mm); z += e[i]; }
        z = warp_sum(z);
        if (lane == 0) red[wid] = z;
        __syncthreads();
        float zz = red[0];
#pragma unroll
        for (int i = 1; i < 8; i++) zz += red[i];
        __syncthreads();

        float inv = 1.f / (zz * (float)NH);
#pragma unroll
        for (int i = 0; i < 8; i++) acc[i] += e[i] * inv;
    }

    float4* outr = (float4*)(attn_mean + (size_t)bs * NS);
    outr[tid] = make_float4(acc[0], acc[1], acc[2], acc[3]);
    outr[256 + tid] = make_float4(acc[4], acc[5], acc[6], acc[7]);
}

// ---------------- launch ----------------------------------------------------------
extern "C" void kernel_launch(void* const* d_in, const int* in_sizes, int n_in,
                              void* d_out, int out_size)
{
    const float* q  = (const float*)d_in[0];
    const float* k  = (const float*)d_in[1];
    const float* v  = (const float*)d_in[2];
    const float* Wq = (const float*)d_in[3];
    const float* Wk = (const float*)d_in[4];
    const float* Wv = (const float*)d_in[5];
    const float* Wo = (const float*)d_in[6];

    float* out = (float*)d_out;                          // [B,S,D]
    float* attn_mean = out + (size_t)NB * NS * ND;       // [B,S,S]

    float *qs, *ks, *vs, *head, *scores;
    cudaGetSymbolAddress((void**)&qs, g_qs);
    cudaGetSymbolAddress((void**)&ks, g_ks);
    cudaGetSymbolAddress((void**)&vs, g_vs);
    cudaGetSymbolAddress((void**)&head, g_head);
    cudaGetSymbolAddress((void**)&scores, g_scores);

    dim3 thr(256);

    // 1. qs = q @ Wq[h], ks = k @ Wk[h]   (scattered [b][h][s][k])
    gemm_proj<<<dim3(1, NB * NS / 64, 2 * NH), thr>>>(q, k, Wq, Wk, qs, ks);

    // 2. vs = v @ Wv   [B*S, 64]
    gemm64<false><<<dim3(1, NB * NS / 64, 1), thr>>>(
        v, Wv, vs, NB * NS, NDK, ND, 0, 0, 0, 1.0f);

    // 3. scores[b,h] = qs[b,h] @ ks[b,h]^T / 8
    gemm64<true><<<dim3(NS / 64, NS / 64, NB * NH), thr>>>(
        qs, ks, scores, NS, NS, NDK,
        (long long)NS * NDK, (long long)NS * NDK, (long long)NS * NS, 0.125f);

    // 4. softmax per row, mean over heads -> attn_mean (output #2)
    softmax_mean<<<NB * NS, thr>>>(scores, attn_mean);

    // 5. head[b] = attn_mean[b] @ vs[b]    (mean over heads already folded in)
    gemm64<false><<<dim3(1, NS / 64, NB), thr>>>(
        attn_mean, vs, head, NS, NDK, NS,
        (long long)NS * NS, (long long)NS * NDK, (long long)NS * NDK, 1.0f);

    // 6. out = head @ Wo    [B*S, 1024]
    gemm64<false><<<dim3(ND / 64, NB * NS / 64, 1), thr>>>(
        head, Wo, out, NB * NS, ND, NDK, 0, 0, 0, 1.0f);
}

// round 3
// speedup vs baseline: 1.7510x; 1.7510x over previous
#include <cuda_runtime.h>
#include <math.h>

#define NB 2
#define NS 2048
#define ND 1024
#define NH 16
#define NDK 64

// ---------------- scratch ----------------------------------------------------------
__device__ float g_qs[NB * NH * NS * NDK];            // [b][h][s][k]
__device__ float g_ks[NB * NH * NS * NDK];            // [b][h][s][k]
__device__ float g_vs[NB * NS * NDK];                 // [b][s][k]
__device__ float g_head[NB * NS * NDK];               // [b][s][k]
__device__ float g_scores[(size_t)NB * NH * NS * NS]; // [b][h][s][t]  536 MB

// ---------------- tf32 mma helpers -------------------------------------------------
__device__ __forceinline__ unsigned f2tf32(float f) {
    unsigned u;
    asm("cvt.rna.tf32.f32 %0, %1;" : "=r"(u) : "f"(f));
    return u;
}

__device__ __forceinline__ void mma_tf32(float c[4], const unsigned a[4], const unsigned b[2]) {
    asm volatile(
        "mma.sync.aligned.m16n8k8.row.col.f32.tf32.tf32.f32 "
        "{%0,%1,%2,%3}, {%4,%5,%6,%7}, {%8,%9}, {%0,%1,%2,%3};\n"
        : "+f"(c[0]), "+f"(c[1]), "+f"(c[2]), "+f"(c[3])
        : "r"(a[0]), "r"(a[1]), "r"(a[2]), "r"(a[3]), "r"(b[0]), "r"(b[1]));
}

// ---------------- scores = qs @ ks^T / 8  (tf32 tensor cores) ----------------------
// grid (NS/128, NS/128, NB*NH), 256 threads (8 warps, warp grid 2m x 4n, warp tile 64x32)
__global__ __launch_bounds__(256) void scores_tf32(
    const float* __restrict__ qs, const float* __restrict__ ks,
    float* __restrict__ scores)
{
    __shared__ unsigned As[128][36];   // [m][k], stride 36 (4 mod 32) -> conflict-free
    __shared__ unsigned Bs[128][36];   // [n][k]

    size_t zoff = (size_t)blockIdx.z * NS * NDK;
    const float* A = qs + zoff;
    const float* B = ks + zoff;
    float* C = scores + (size_t)blockIdx.z * NS * NS;

    int m0 = blockIdx.y * 128, n0 = blockIdx.x * 128;
    int tid = threadIdx.x;
    int warp = tid >> 5, lane = tid & 31;
    int wm = (warp >> 2) * 64, wn = (warp & 3) * 32;
    int g = lane >> 2, t = lane & 3;

    float acc[4][4][4] = {};

    for (int k0 = 0; k0 < NDK; k0 += 32) {
#pragma unroll
        for (int i = 0; i < 4; i++) {
            int id = tid + i * 256;          // 0..1023
            int row = id >> 3;               // 0..127
            int c4 = (id & 7) * 4;           // 0..28
            float4 va = *(const float4*)(A + (size_t)(m0 + row) * NDK + k0 + c4);
            As[row][c4 + 0] = f2tf32(va.x);
            As[row][c4 + 1] = f2tf32(va.y);
            As[row][c4 + 2] = f2tf32(va.z);
            As[row][c4 + 3] = f2tf32(va.w);
            float4 vb = *(const float4*)(B + (size_t)(n0 + row) * NDK + k0 + c4);
            Bs[row][c4 + 0] = f2tf32(vb.x);
            Bs[row][c4 + 1] = f2tf32(vb.y);
            Bs[row][c4 + 2] = f2tf32(vb.z);
            Bs[row][c4 + 3] = f2tf32(vb.w);
        }
        __syncthreads();

#pragma unroll
        for (int kk = 0; kk < 32; kk += 8) {
            unsigned af[4][4], bf[4][2];
#pragma unroll
            for (int i = 0; i < 4; i++) {
                int mr = wm + i * 16;
                af[i][0] = As[mr + g][kk + t];
                af[i][1] = As[mr + g + 8][kk + t];
                af[i][2] = As[mr + g][kk + t + 4];
                af[i][3] = As[mr + g + 8][kk + t + 4];
            }
#pragma unroll
            for (int j = 0; j < 4; j++) {
                int nr = wn + j * 8;
                bf[j][0] = Bs[nr + g][kk + t];
                bf[j][1] = Bs[nr + g][kk + t + 4];
            }
#pragma unroll
            for (int i = 0; i < 4; i++)
#pragma unroll
                for (int j = 0; j < 4; j++) mma_tf32(acc[i][j], af[i], bf[j]);
        }
        __syncthreads();
    }

    const float alpha = 0.125f;
#pragma unroll
    for (int i = 0; i < 4; i++) {
#pragma unroll
        for (int j = 0; j < 4; j++) {
            int row = m0 + wm + i * 16 + g;
            int col = n0 + wn + j * 8 + 2 * t;
            float2 v0 = make_float2(acc[i][j][0] * alpha, acc[i][j][1] * alpha);
            float2 v1 = make_float2(acc[i][j][2] * alpha, acc[i][j][3] * alpha);
            *(float2*)(C + (size_t)row * NS + col) = v0;
            *(float2*)(C + (size_t)(row + 8) * NS + col) = v1;
        }
    }
}

// ---------------- per-head Q/K projections (tf32 tensor cores) ---------------------
// grid (1, NB*NS/128, 2*NH), 128 threads (4 warps, warp grid 2m x 2n, warp tile 64x32)
// z: h = z & 15, which = z >> 4 (0 -> q/Wq/qs, 1 -> k/Wk/ks)
__global__ __launch_bounds__(128) void proj_tf32(
    const float* __restrict__ in_q, const float* __restrict__ in_k,
    const float* __restrict__ Wq, const float* __restrict__ Wk,
    float* __restrict__ out_qs, float* __restrict__ out_ks)
{
    __shared__ unsigned As[128][36];   // [m][k]
    __shared__ unsigned Bs[64][36];    // [n][k]

    int z = blockIdx.z;
    int h = z & (NH - 1);
    int which = z >> 4;
    const float* A = which ? in_k : in_q;
    const float* W = (which ? Wk : Wq) + (size_t)h * ND * NDK;
    float* outp = which ? out_ks : out_qs;

    int m0 = blockIdx.y * 128;
    int b = m0 / NS;
    int srow = m0 % NS;
    float* C = outp + ((size_t)(b * NH + h) * NS + srow) * NDK;

    int tid = threadIdx.x;
    int warp = tid >> 5, lane = tid & 31;
    int wm = (warp >> 1) * 64, wn = (warp & 1) * 32;
    int g = lane >> 2, t = lane & 3;

    float acc[4][4][4] = {};

    for (int k0 = 0; k0 < ND; k0 += 32) {
        // A chunk: 128 x 32 floats = 1024 float4, 8 per thread
#pragma unroll
        for (int i = 0; i < 8; i++) {
            int id = tid + i * 128;
            int row = id >> 3;
            int c4 = (id & 7) * 4;
            float4 va = *(const float4*)(A + (size_t)(m0 + row) * ND + k0 + c4);
            As[row][c4 + 0] = f2tf32(va.x);
            As[row][c4 + 1] = f2tf32(va.y);
            As[row][c4 + 2] = f2tf32(va.z);
            As[row][c4 + 3] = f2tf32(va.w);
        }
        // W chunk: [32 k][64 n] -> Bs[n][k], 512 float4, 4 per thread
#pragma unroll
        for (int i = 0; i < 4; i++) {
            int id = tid + i * 128;
            int kr = id >> 4;            // 0..31
            int nc = (id & 15) * 4;      // 0..60
            float4 vb = *(const float4*)(W + (size_t)(k0 + kr) * NDK + nc);
            Bs[nc + 0][kr] = f2tf32(vb.x);
            Bs[nc + 1][kr] = f2tf32(vb.y);
            Bs[nc + 2][kr] = f2tf32(vb.z);
            Bs[nc + 3][kr] = f2tf32(vb.w);
        }
        __syncthreads();

#pragma unroll
        for (int kk = 0; kk < 32; kk += 8) {
            unsigned af[4][4], bf[4][2];
#pragma unroll
            for (int i = 0; i < 4; i++) {
                int mr = wm + i * 16;
                af[i][0] = As[mr + g][kk + t];
                af[i][1] = As[mr + g + 8][kk + t];
                af[i][2] = As[mr + g][kk + t + 4];
                af[i][3] = As[mr + g + 8][kk + t + 4];
            }
#pragma unroll
            for (int j = 0; j < 4; j++) {
                int nr = wn + j * 8;
                bf[j][0] = Bs[nr + g][kk + t];
                bf[j][1] = Bs[nr + g][kk + t + 4];
            }
#pragma unroll
            for (int i = 0; i < 4; i++)
#pragma unroll
                for (int j = 0; j < 4; j++) mma_tf32(acc[i][j], af[i], bf[j]);
        }
        __syncthreads();
    }

#pragma unroll
    for (int i = 0; i < 4; i++) {
#pragma unroll
        for (int j = 0; j < 4; j++) {
            int row = wm + i * 16 + g;
            int col = wn + j * 8 + 2 * t;
            float2 v0 = make_float2(acc[i][j][0], acc[i][j][1]);
            float2 v1 = make_float2(acc[i][j][2], acc[i][j][3]);
            *(float2*)(C + (size_t)row * NDK + col) = v0;
            *(float2*)(C + (size_t)(row + 8) * NDK + col) = v1;
        }
    }
}

// ---------------- generic 64x64-tile fp32 SIMT GEMM (small GEMMs) ------------------
template <bool BT>
__global__ __launch_bounds__(256) void gemm64(
    const float* __restrict__ Ab, const float* __restrict__ Bb, float* __restrict__ Cb,
    int M, int N, int K, long long sA, long long sB, long long sC, float alpha)
{
    const int BM = 64, BN = 64, BK = 16;
    __shared__ float As[BK][BM + 4];
    __shared__ float Bs[BK][BN + 4];

    const float* A = Ab + (size_t)blockIdx.z * sA;
    const float* B = Bb + (size_t)blockIdx.z * sB;
    float* C = Cb + (size_t)blockIdx.z * sC;

    int tid = threadIdx.x;
    int tx = tid & 15, ty = tid >> 4;
    int m0 = blockIdx.y * BM, n0 = blockIdx.x * BN;

    int la_r = tid >> 2;
    int la_c = (tid & 3) * 4;

    float acc[4][4] = {};

    for (int k0 = 0; k0 < K; k0 += BK) {
        float4 av = *(const float4*)(A + (size_t)(m0 + la_r) * K + k0 + la_c);
        As[la_c + 0][la_r] = av.x;
        As[la_c + 1][la_r] = av.y;
        As[la_c + 2][la_r] = av.z;
        As[la_c + 3][la_r] = av.w;

        if (BT) {
            float4 bv = *(const float4*)(B + (size_t)(n0 + la_r) * K + k0 + la_c);
            Bs[la_c + 0][la_r] = bv.x;
            Bs[la_c + 1][la_r] = bv.y;
            Bs[la_c + 2][la_r] = bv.z;
            Bs[la_c + 3][la_r] = bv.w;
        } else {
            int br = tid >> 4;
            int bc = (tid & 15) * 4;
            float4 bv = *(const float4*)(B + (size_t)(k0 + br) * N + n0 + bc);
            *(float4*)&Bs[br][bc] = bv;
        }
        __syncthreads();

#pragma unroll
        for (int k = 0; k < BK; k++) {
            float a[4], b[4];
#pragma unroll
            for (int i = 0; i < 4; i++) a[i] = As[k][ty * 4 + i];
#pragma unroll
            for (int j = 0; j < 4; j++) b[j] = Bs[k][tx * 4 + j];
#pragma unroll
            for (int i = 0; i < 4; i++)
#pragma unroll
                for (int j = 0; j < 4; j++) acc[i][j] += a[i] * b[j];
        }
        __syncthreads();
    }

#pragma unroll
    for (int i = 0; i < 4; i++) {
        int m = m0 + ty * 4 + i;
        float4 v = make_float4(acc[i][0] * alpha, acc[i][1] * alpha,
                               acc[i][2] * alpha, acc[i][3] * alpha);
        *(float4*)(C + (size_t)m * N + n0 + tx * 4) = v;
    }
}

// ---------------- softmax over each score row + mean over heads --------------------
__device__ __forceinline__ float warp_max(float v) {
#pragma unroll
    for (int o = 16; o; o >>= 1) v = fmaxf(v, __shfl_xor_sync(0xFFFFFFFFu, v, o));
    return v;
}
__device__ __forceinline__ float warp_sum(float v) {
#pragma unroll
    for (int o = 16; o; o >>= 1) v += __shfl_xor_sync(0xFFFFFFFFu, v, o);
    return v;
}

__global__ __launch_bounds__(256) void softmax_mean(
    const float* __restrict__ scores, float* __restrict__ attn_mean)
{
    __shared__ float red[8];
    int bs = blockIdx.x;
    int tid = threadIdx.x;
    int wid = tid >> 5, lane = tid & 31;

    float acc[8] = {0.f, 0.f, 0.f, 0.f, 0.f, 0.f, 0.f, 0.f};

    for (int h = 0; h < NH; h++) {
        int b = bs / NS, s = bs % NS;
        const float4* row =
            (const float4*)(scores + ((size_t)(b * NH + h) * NS + s) * NS);
        float4 v0 = row[tid];
        float4 v1 = row[256 + tid];
        float vals[8] = {v0.x, v0.y, v0.z, v0.w, v1.x, v1.y, v1.z, v1.w};

        float m = vals[0];
#pragma unroll
        for (int i = 1; i < 8; i++) m = fmaxf(m, vals[i]);
        m = warp_max(m);
        if (lane == 0) red[wid] = m;
        __syncthreads();
        float mm = red[0];
#pragma unroll
        for (int i = 1; i < 8; i++) mm = fmaxf(mm, red[i]);
        __syncthreads();

        float e[8];
        float z = 0.f;
#pragma unroll
        for (int i = 0; i < 8; i++) { e[i] = __expf(vals[i] - mm); z += e[i]; }
        z = warp_sum(z);
        if (lane == 0) red[wid] = z;
        __syncthreads();
        float zz = red[0];
#pragma unroll
        for (int i = 1; i < 8; i++) zz += red[i];
        __syncthreads();

        float inv = 1.f / (zz * (float)NH);
#pragma unroll
        for (int i = 0; i < 8; i++) acc[i] += e[i] * inv;
    }

    float4* outr = (float4*)(attn_mean + (size_t)bs * NS);
    outr[tid] = make_float4(acc[0], acc[1], acc[2], acc[3]);
    outr[256 + tid] = make_float4(acc[4], acc[5], acc[6], acc[7]);
}

// ---------------- launch ----------------------------------------------------------
extern "C" void kernel_launch(void* const* d_in, const int* in_sizes, int n_in,
                              void* d_out, int out_size)
{
    const float* q  = (const float*)d_in[0];
    const float* k  = (const float*)d_in[1];
    const float* v  = (const float*)d_in[2];
    const float* Wq = (const float*)d_in[3];
    const float* Wk = (const float*)d_in[4];
    const float* Wv = (const float*)d_in[5];
    const float* Wo = (const float*)d_in[6];

    float* out = (float*)d_out;                          // [B,S,D]
    float* attn_mean = out + (size_t)NB * NS * ND;       // [B,S,S]

    float *qs, *ks, *vs, *head, *scores;
    cudaGetSymbolAddress((void**)&qs, g_qs);
    cudaGetSymbolAddress((void**)&ks, g_ks);
    cudaGetSymbolAddress((void**)&vs, g_vs);
    cudaGetSymbolAddress((void**)&head, g_head);
    cudaGetSymbolAddress((void**)&scores, g_scores);

    // 1. qs = q @ Wq[h], ks = k @ Wk[h]   (tf32 tensor cores, scattered [b][h][s][k])
    proj_tf32<<<dim3(1, NB * NS / 128, 2 * NH), 128>>>(q, k, Wq, Wk, qs, ks);

    // 2. vs = v @ Wv   [B*S, 64]
    gemm64<false><<<dim3(1, NB * NS / 64, 1), 256>>>(
        v, Wv, vs, NB * NS, NDK, ND, 0, 0, 0, 1.0f);

    // 3. scores[b,h] = qs[b,h] @ ks[b,h]^T / 8   (tf32 tensor cores)
    scores_tf32<<<dim3(NS / 128, NS / 128, NB * NH), 256>>>(qs, ks, scores);

    // 4. softmax per row, mean over heads -> attn_mean (output #2)
    softmax_mean<<<NB * NS, 256>>>(scores, attn_mean);

    // 5. head[b] = attn_mean[b] @ vs[b]
    gemm64<false><<<dim3(1, NS / 64, NB), 256>>>(
        attn_mean, vs, head, NS, NDK, NS,
        (long long)NS * NS, (long long)NS * NDK, (long long)NS * NDK, 1.0f);

    // 6. out = head @ Wo    [B*S, 1024]
    gemm64<false><<<dim3(ND / 64, NB * NS / 64, 1), 256>>>(
        head, Wo, out, NB * NS, ND, NDK, 0, 0, 0, 1.0f);
}